// round 9
// baseline (speedup 1.0000x reference)
#include <cuda_runtime.h>
#include <math.h>

// Problem constants (fixed by the dataset)
#define NCAP 100000
#define ECAP 1600000
#define DIM  64
#define HID  128

#define BM   64          // rows per fused-kernel chunk
#define NCHCAP ((NCAP + BM - 1) / BM)
#define OFF  296         // pipeline offset (one full 2-block/SM wave)

// ---------------- scratch (device globals; no runtime allocation) ----------
static __device__ __align__(128) int   d_cnt[NCAP];
static __device__ __align__(128) int   d_rowptr[NCAP + 1];
static __device__ __align__(128) int   d_cursor[NCAP];
static __device__ __align__(128) int   d_bsum[256];
static __device__ __align__(128) int   d_flag[NCHCAP + 8];
static __device__ __align__(128) int   d_col[ECAP];
static __device__ __align__(128) float d_dinv[NCAP];
static __device__ __align__(128) float d_invdeg[NCAP];
static __device__ __align__(128) float d_x[NCAP * DIM];      // renormed entity emb
static __device__ __align__(128) float d_agg1[NCAP * DIM];   // Ahat(x)
static __device__ __align__(128) float d_g[NCAP * DIM];      // relu(Ahat(x)W1+b1) @ W2

// ---------------- f32x2 packed math (Blackwell FFMA2) -----------------------
__device__ __forceinline__ unsigned long long pk2(float lo, float hi) {
    unsigned long long r;
    asm("mov.b64 %0, {%1, %2};" : "=l"(r) : "r"(__float_as_uint(lo)), "r"(__float_as_uint(hi)));
    return r;
}
__device__ __forceinline__ unsigned long long fma2(unsigned long long a,
                                                   unsigned long long b,
                                                   unsigned long long c) {
    unsigned long long d;
    asm("fma.rn.f32x2 %0, %1, %2, %3;" : "=l"(d) : "l"(a), "l"(b), "l"(c));
    return d;
}
__device__ __forceinline__ float2 upk2(unsigned long long v) {
    unsigned int lo, hi;
    asm("mov.b64 {%0, %1}, %2;" : "=r"(lo), "=r"(hi) : "l"(v));
    return make_float2(__uint_as_float(lo), __uint_as_float(hi));
}

// ---------------- degree counting + flag zero --------------------------------
__global__ void zero_cnt_kernel(int n, int nch) {
    int i = blockIdx.x * blockDim.x + threadIdx.x;
    if (i < n) d_cnt[i] = 0;
    if (i < nch) d_flag[i] = 0;
}

__global__ void count_deg_kernel(const int* __restrict__ dst, int E) {
    int e = blockIdx.x * blockDim.x + threadIdx.x;
    if (e < E) atomicAdd(&d_cnt[dst[e]], 1);
}

// ---------------- prefix sum (chunked) --------------------------------------
__global__ void scan_chunk_kernel(int n) {
    __shared__ int s[1024];
    int t = threadIdx.x;
    int i = blockIdx.x * 1024 + t;
    int v = (i < n) ? d_cnt[i] : 0;
    s[t] = v;
    __syncthreads();
    for (int off = 1; off < 1024; off <<= 1) {
        int add = (t >= off) ? s[t - off] : 0;
        __syncthreads();
        s[t] += add;
        __syncthreads();
    }
    if (i < n) d_rowptr[i] = s[t] - v;   // exclusive
    if (t == 1023) d_bsum[blockIdx.x] = s[1023];
}

// parallel exclusive scan of block sums (nb <= 128)
__global__ void scan_bsums_kernel(int nb) {
    __shared__ int ws[4];
    int t = threadIdx.x;
    int lane = t & 31, w = t >> 5;
    int v = (t < nb) ? d_bsum[t] : 0;
    int s = v;
    #pragma unroll
    for (int o = 1; o < 32; o <<= 1) {
        int u = __shfl_up_sync(0xffffffffu, s, o);
        if (lane >= o) s += u;
    }
    if (lane == 31) ws[w] = s;
    __syncthreads();
    int add = 0;
    #pragma unroll
    for (int i = 0; i < 4; i++) if (i < w) add += ws[i];
    if (t < nb) d_bsum[t] = s - v + add;   // exclusive
}

__global__ void finalize_rowptr_kernel(int n, int Etot) {
    int i = blockIdx.x * blockDim.x + threadIdx.x;
    if (i < n) {
        int rp = d_rowptr[i] + d_bsum[i >> 10];
        d_rowptr[i] = rp;
        d_cursor[i] = rp;
        float deg = (float)(d_cnt[i] + 1);   // +1 self loop
        d_dinv[i]   = rsqrtf(deg);
        d_invdeg[i] = 1.0f / deg;
    }
    if (i == 0) d_rowptr[n] = Etot;
}

__global__ void fill_csr_kernel(const int* __restrict__ src,
                                const int* __restrict__ dst, int E) {
    int e = blockIdx.x * blockDim.x + threadIdx.x;
    if (e < E) {
        int d = dst[e];
        int p = atomicAdd(&d_cursor[d], 1);
        d_col[p] = src[e];
    }
}

// ---------------- entity renorm (max_norm = 1) ------------------------------
__global__ void renorm_entities_kernel(const float* __restrict__ emb, int n) {
    int gtid = blockIdx.x * blockDim.x + threadIdx.x;
    int row = gtid >> 5;
    int lane = gtid & 31;
    if (row >= n) return;
    float2 v = *(const float2*)(emb + (size_t)row * DIM + lane * 2);
    float ss = v.x * v.x + v.y * v.y;
    #pragma unroll
    for (int o = 16; o; o >>= 1) ss += __shfl_xor_sync(0xffffffffu, ss, o);
    float nrm = sqrtf(ss);
    float sc = fminf(1.0f, 1.0f / fmaxf(nrm, 1e-12f));
    float2 o2 = make_float2(v.x * sc, v.y * sc);
    *(float2*)(d_x + (size_t)row * DIM + lane * 2) = o2;
}

// ---------------- fused agg1 + GEMM1 + GEMM2, software-pipelined -------------
// Block b: (a) aggregate chunk b (64 rows) -> d_agg1, set flag[b];
//          (b) wait flag[b-OFF], then G = relu(A@W1+b1)@W2 for chunk b-OFF.
// smem: sU = union{ sA dup [64][130] (each a stored twice -> LDS64 gives (a,a)),
//                   sH [64][130] } | sW1 paired [64*128] | sW2 [128*64]
#define SU_STRIDE 130
#define FUSED_SMEM_FLOATS (BM * SU_STRIDE + 64 * 128 + 128 * 64)
#define FUSED_SMEM_BYTES  (FUSED_SMEM_FLOATS * 4)

__global__ __launch_bounds__(128, 2)
void fused_pipeline_kernel(const float* __restrict__ W1, const float* __restrict__ b1,
                           const float* __restrict__ W2, int n, int nch) {
    extern __shared__ float smem[];
    float* sU  = smem;                       // [BM][SU_STRIDE]
    float* sW1 = sU + BM * SU_STRIDE;        // paired layout [64][128]
    float* sW2 = sW1 + 64 * 128;             // [128][64]

    const int tid = threadIdx.x;
    const int b = blockIdx.x;
    const int ca = b;                        // agg chunk
    const int cg = b - OFF;                  // gemm chunk
    const bool doG = (cg >= 0);

    // ---- preload weights (independent of flags) ----
    if (doG) {
        #pragma unroll
        for (int t = tid; t < 64 * 128; t += 128) {
            int k = t >> 7, c = t & 127;
            int txp = c & 15, m = c >> 4;
            int slot = (((m >> 1) * 16 + txp) << 1) + (m & 1);
            sW1[k * 128 + slot] = W1[t];
        }
        #pragma unroll
        for (int t = tid; t < 128 * 16; t += 128) {
            *(float4*)&sW2[t * 4] = *(const float4*)(W2 + t * 4);
        }
    }

    // ---- phase A: aggregate 64 rows of chunk ca ----
    if (ca < nch) {
        int warp = tid >> 5, lane = tid & 31;
        int rowBase = ca * BM;
        for (int rr = warp; rr < BM; rr += 4) {
            int r = rowBase + rr;
            if (r >= n) break;
            int beg = d_rowptr[r], end = d_rowptr[r + 1];
            float2 acc = make_float2(0.f, 0.f);
            for (int e = beg; e < end; e++) {
                int s = d_col[e];
                float w = d_dinv[s];
                float2 xs = *(const float2*)(d_x + (size_t)s * DIM + lane * 2);
                acc.x = fmaf(w, xs.x, acc.x);
                acc.y = fmaf(w, xs.y, acc.y);
            }
            float di = d_dinv[r], id = d_invdeg[r];
            float2 self = *(const float2*)(d_x + (size_t)r * DIM + lane * 2);
            float2 o = make_float2(di * acc.x + id * self.x,
                                   di * acc.y + id * self.y);
            *(float2*)(d_agg1 + (size_t)r * DIM + lane * 2) = o;
        }
        __syncthreads();
        if (tid == 0) {
            __threadfence();
            atomicExch(&d_flag[ca], 1);
        }
    }

    if (!doG) return;

    // ---- wait for producer of chunk cg ----
    if (tid == 0) {
        while (atomicAdd(&d_flag[cg], 0) == 0) __nanosleep(64);
        __threadfence();
    }
    __syncthreads();

    const int tx = tid & 15, ty = tid >> 4;   // 16 x 8
    const int r0 = ty * 8;
    const int rowBase = cg * BM;

    // ---- load A tile (L2, bypass L1) into duplicated smem layout ----
    #pragma unroll
    for (int t = tid; t < BM * 16; t += 128) {
        int r = t >> 4, k4 = t & 15;
        float4 v = make_float4(0.f, 0.f, 0.f, 0.f);
        int gr = rowBase + r;
        if (gr < n) v = __ldcg((const float4*)(d_agg1 + (size_t)gr * DIM + k4 * 4));
        float* p = &sU[r * SU_STRIDE + k4 * 8];
        *(float2*)(p + 0) = make_float2(v.x, v.x);
        *(float2*)(p + 2) = make_float2(v.y, v.y);
        *(float2*)(p + 4) = make_float2(v.z, v.z);
        *(float2*)(p + 6) = make_float2(v.w, v.w);
    }
    __syncthreads();

    // ---- stage 1: acc[i][j] = row r0+i, col pair (tx+32j, tx+32j+16) ----
    unsigned long long acc[8][4];
    #pragma unroll
    for (int i = 0; i < 8; i++)
        #pragma unroll
        for (int j = 0; j < 4; j++) acc[i][j] = 0ull;

    #pragma unroll 4
    for (int k = 0; k < 64; k++) {
        unsigned long long bd[4];
        #pragma unroll
        for (int j = 0; j < 4; j++)
            bd[j] = *(const unsigned long long*)&sW1[k * 128 + ((j * 16 + tx) << 1)];
        #pragma unroll
        for (int i = 0; i < 8; i++) {
            unsigned long long ad =
                *(const unsigned long long*)&sU[(r0 + i) * SU_STRIDE + 2 * k];
            #pragma unroll
            for (int j = 0; j < 4; j++)
                acc[i][j] = fma2(ad, bd[j], acc[i][j]);
        }
    }
    __syncthreads();   // sA (in sU) dead; safe to overwrite as sH

    // ---- bias + relu + write H into sU (stride SU_STRIDE) ----
    float b1c[8];
    #pragma unroll
    for (int j = 0; j < 4; j++) {
        b1c[j * 2]     = b1[tx + 32 * j];
        b1c[j * 2 + 1] = b1[tx + 32 * j + 16];
    }
    #pragma unroll
    for (int i = 0; i < 8; i++) {
        int rr = (r0 + i) * SU_STRIDE;
        #pragma unroll
        for (int j = 0; j < 4; j++) {
            float2 v = upk2(acc[i][j]);
            int c = tx + 32 * j;
            sU[rr + c]      = fmaxf(v.x + b1c[j * 2], 0.f);
            sU[rr + c + 16] = fmaxf(v.y + b1c[j * 2 + 1], 0.f);
        }
    }
    __syncthreads();

    // ---- stage 2: acc2[i][j] = row r0+i, cols (4tx+2j, 4tx+2j+1) ----
    unsigned long long acc2[8][2];
    #pragma unroll
    for (int i = 0; i < 8; i++) { acc2[i][0] = 0ull; acc2[i][1] = 0ull; }

    #pragma unroll 4
    for (int k = 0; k < 128; k++) {
        unsigned long long bd0 = *(const unsigned long long*)&sW2[k * 64 + 4 * tx];
        unsigned long long bd1 = *(const unsigned long long*)&sW2[k * 64 + 4 * tx + 2];
        #pragma unroll
        for (int i = 0; i < 8; i++) {
            float a = sU[(r0 + i) * SU_STRIDE + k];
            unsigned long long ad = pk2(a, a);
            acc2[i][0] = fma2(ad, bd0, acc2[i][0]);
            acc2[i][1] = fma2(ad, bd1, acc2[i][1]);
        }
    }

    // ---- store G (float4, coalesced) ----
    #pragma unroll
    for (int i = 0; i < 8; i++) {
        int gr = rowBase + r0 + i;
        if (gr < n) {
            float2 v0 = upk2(acc2[i][0]);
            float2 v1 = upk2(acc2[i][1]);
            float4 o = make_float4(v0.x, v0.y, v1.x, v1.y);
            *(float4*)&d_g[(size_t)gr * DIM + 4 * tx] = o;
        }
    }
}

// ---------------- final: agg2 restricted to batch items + user dot ----------
__global__ void final_kernel(const int* __restrict__ u,
                             const int* __restrict__ it,
                             const float* __restrict__ user_emb,
                             const float* __restrict__ b2,
                             float* __restrict__ out, int B) {
    int gtid = blockIdx.x * blockDim.x + threadIdx.x;
    int w = gtid >> 5;
    int lane = gtid & 31;
    if (w >= B) return;

    int r = it[w];
    int beg = d_rowptr[r], end = d_rowptr[r + 1];
    float2 acc = make_float2(0.f, 0.f);
    for (int e = beg; e < end; e++) {
        int s = d_col[e];
        float wt = d_dinv[s];
        float2 gs = *(const float2*)(d_g + (size_t)s * DIM + lane * 2);
        acc.x = fmaf(wt, gs.x, acc.x);
        acc.y = fmaf(wt, gs.y, acc.y);
    }
    float di = d_dinv[r], id = d_invdeg[r];
    float2 gr = *(const float2*)(d_g + (size_t)r * DIM + lane * 2);
    float2 item = make_float2(di * acc.x + id * gr.x + b2[lane * 2 + 0],
                              di * acc.y + id * gr.y + b2[lane * 2 + 1]);

    int uu = u[w];
    float2 uv = *(const float2*)(user_emb + (size_t)uu * DIM + lane * 2);
    float ss = uv.x * uv.x + uv.y * uv.y;
    #pragma unroll
    for (int o = 16; o; o >>= 1) ss += __shfl_xor_sync(0xffffffffu, ss, o);
    float sc = fminf(1.0f, 1.0f / fmaxf(sqrtf(ss), 1e-12f));

    float dot = (uv.x * sc) * item.x + (uv.y * sc) * item.y;
    #pragma unroll
    for (int o = 16; o; o >>= 1) dot += __shfl_xor_sync(0xffffffffu, dot, o);

    if (lane == 0) out[w] = 1.0f / (1.0f + expf(-dot));
}

// ---------------- launch ----------------------------------------------------
extern "C" void kernel_launch(void* const* d_in, const int* in_sizes, int n_in,
                              void* d_out, int out_size) {
    const int*   u          = (const int*)d_in[0];
    const int*   it         = (const int*)d_in[1];
    const int*   edges      = (const int*)d_in[2];
    const float* user_emb   = (const float*)d_in[3];
    const float* entity_emb = (const float*)d_in[4];
    const float* W1         = (const float*)d_in[5];
    const float* b1         = (const float*)d_in[6];
    const float* W2         = (const float*)d_in[7];
    const float* b2         = (const float*)d_in[8];
    float*       out        = (float*)d_out;

    int B = in_sizes[0];
    int E = in_sizes[2] / 2;
    int n = in_sizes[4] / DIM;
    if (n > NCAP) n = NCAP;
    if (E > ECAP) E = ECAP;

    const int* src = edges;
    const int* dst = edges + E;
    int nch = (n + BM - 1) / BM;

    const int T = 256;

    // entity renorm first (independent of graph structure)
    renorm_entities_kernel<<<(n + 7) / 8, T>>>(entity_emb, n);

    // degree counts (+ flag zeroing)
    zero_cnt_kernel<<<(n + T - 1) / T, T>>>(n, nch);
    count_deg_kernel<<<(E + T - 1) / T, T>>>(dst, E);

    // CSR build
    int nb = (n + 1023) / 1024;
    scan_chunk_kernel<<<nb, 1024>>>(n);
    scan_bsums_kernel<<<1, 128>>>(nb);
    finalize_rowptr_kernel<<<(n + T - 1) / T, T>>>(n, E);
    fill_csr_kernel<<<(E + T - 1) / T, T>>>(src, dst, E);

    // fused: agg1 chunk b  ->  relu(A@W1+b1)@W2 on chunk b-OFF (pipelined)
    cudaFuncSetAttribute(fused_pipeline_kernel,
                         cudaFuncAttributeMaxDynamicSharedMemorySize,
                         FUSED_SMEM_BYTES);
    fused_pipeline_kernel<<<nch + OFF, 128, FUSED_SMEM_BYTES>>>(W1, b1, W2, n, nch);

    // restricted layer-2 aggregation fused with user dot + sigmoid
    final_kernel<<<(B + 7) / 8, T>>>(u, it, user_emb, b2, out, B);
}